// round 4
// baseline (speedup 1.0000x reference)
#include <cuda_runtime.h>
#include <cstdint>
#include <cstddef>

// Problem constants (fixed shapes)
#define BATCH   4
#define SEQ     1024
#define NHEADS  32
#define NKV     8
#define HDIM    128
#define NTOK    (BATCH * SEQ)
#define NBLOCKS 32
#define BLOCKSZ 256

#define BM 64          // q rows per CTA
#define BN 128         // keys per iteration
#define PADW 132       // padded row stride (floats): 132 mod 32 == 4 -> conflict-free LDS.128
#define NTHREADS 256   // 16 x 16 thread grid

// scale = float(bfloat16(1/sqrt(128))) = 0x3DB50000
#define ATTN_SCALE 0.08837890625f

#define O_ELEMS     ((size_t)NTOK * NHEADS * HDIM)                 // 16,777,216
#define CACHE_ELEMS ((size_t)NBLOCKS * BLOCKSZ * NKV * HDIM)       // 8,388,608

#define SMEM_BYTES ((BM + BN + BN + BM) * PADW * 4)                // 202,752 B

// ---------------------------------------------------------------------------
// Flash attention (causal, GQA 4:1), fp32, register-tiled 4x8 per thread.
// grid = (SEQ/BM, NHEADS, BATCH), block = 256 threads.
// ---------------------------------------------------------------------------
__global__ __launch_bounds__(NTHREADS, 1)
void flash_attn_kernel(const float* __restrict__ q,
                       const float* __restrict__ k,
                       const float* __restrict__ v,
                       float* __restrict__ o)
{
    extern __shared__ float smem[];
    float* Qs = smem;                  // [BM][PADW]
    float* Ks = Qs + BM * PADW;        // [BN][PADW]
    float* Vs = Ks + BN * PADW;        // [BN][PADW]
    float* Ps = Vs + BN * PADW;        // [BM][PADW]

    const int qt  = blockIdx.x;        // q tile: 0..15
    const int h   = blockIdx.y;        // head
    const int b   = blockIdx.z;        // batch
    const int kvh = h >> 2;            // GQA: N_REP = 4

    const int tid  = threadIdx.x;
    const int warp = tid >> 5;
    const int lane = tid & 31;
    const int tx   = tid & 15;
    const int ty   = tid >> 4;

    // ---- load Q tile (64 rows x 128), coalesced float4, one warp per row ----
    {
        const float* qb = q + ((size_t)(b * SEQ + qt * BM) * NHEADS + h) * HDIM;
        #pragma unroll
        for (int r = warp; r < BM; r += 8) {
            const float4 val = ((const float4*)(qb + (size_t)r * NHEADS * HDIM))[lane];
            *(float4*)&Qs[r * PADW + lane * 4] = val;
        }
    }

    float acc[4][8];
    float mi[4], li[4];
    #pragma unroll
    for (int i = 0; i < 4; ++i) {
        mi[i] = -1e30f; li[i] = 0.0f;
        #pragma unroll
        for (int d = 0; d < 8; ++d) acc[i][d] = 0.0f;
    }

    const int kend = (qt + 1) * BM;            // causal key limit (exclusive)
    const int nkt  = (kend + BN - 1) / BN;     // number of key tiles

    for (int kt = 0; kt < nkt; ++kt) {
        const int n0 = kt * BN;

        // ---- load K, V tiles (128 rows x 128) ----
        {
            const float* kb = k + ((size_t)(b * SEQ + n0) * NKV + kvh) * HDIM;
            const float* vb = v + ((size_t)(b * SEQ + n0) * NKV + kvh) * HDIM;
            #pragma unroll
            for (int r = warp; r < BN; r += 8) {
                *(float4*)&Ks[r * PADW + lane * 4] =
                    ((const float4*)(kb + (size_t)r * NKV * HDIM))[lane];
                *(float4*)&Vs[r * PADW + lane * 4] =
                    ((const float4*)(vb + (size_t)r * NKV * HDIM))[lane];
            }
        }
        __syncthreads();

        // ---- GEMM1: S[4][8] = Q(rows ty+16i) . K^T(cols tx+16j) ----
        float sreg[4][8];
        #pragma unroll
        for (int i = 0; i < 4; ++i)
            #pragma unroll
            for (int j = 0; j < 8; ++j) sreg[i][j] = 0.0f;

        #pragma unroll 2
        for (int kk = 0; kk < HDIM; kk += 4) {
            float4 qv[4];
            #pragma unroll
            for (int i = 0; i < 4; ++i)
                qv[i] = *(const float4*)&Qs[(ty + 16 * i) * PADW + kk];
            #pragma unroll
            for (int j = 0; j < 8; ++j) {
                const float4 kv = *(const float4*)&Ks[(tx + 16 * j) * PADW + kk];
                #pragma unroll
                for (int i = 0; i < 4; ++i) {
                    float s = sreg[i][j];
                    s = fmaf(qv[i].x, kv.x, s);
                    s = fmaf(qv[i].y, kv.y, s);
                    s = fmaf(qv[i].z, kv.z, s);
                    s = fmaf(qv[i].w, kv.w, s);
                    sreg[i][j] = s;
                }
            }
        }

        // ---- online softmax (rows owned by 16-lane groups: fixed ty, tx=0..15) ----
        #pragma unroll
        for (int i = 0; i < 4; ++i) {
            const int mg = qt * BM + ty + 16 * i;   // global q row
            float rmax = -1e30f;
            #pragma unroll
            for (int j = 0; j < 8; ++j) {
                const int ng = n0 + tx + 16 * j;    // global key row
                float sv = (ng <= mg) ? sreg[i][j] * ATTN_SCALE : -1e30f;
                sreg[i][j] = sv;
                rmax = fmaxf(rmax, sv);
            }
            #pragma unroll
            for (int off = 8; off > 0; off >>= 1)
                rmax = fmaxf(rmax, __shfl_xor_sync(0xffffffffu, rmax, off));

            const float mnew = fmaxf(mi[i], rmax);
            const float corr = __expf(mi[i] - mnew);
            mi[i] = mnew;

            float rsum = 0.0f;
            #pragma unroll
            for (int j = 0; j < 8; ++j) {
                const float p = __expf(sreg[i][j] - mnew);
                sreg[i][j] = p;
                rsum += p;
            }
            #pragma unroll
            for (int off = 8; off > 0; off >>= 1)
                rsum += __shfl_xor_sync(0xffffffffu, rsum, off);

            li[i] = li[i] * corr + rsum;
            #pragma unroll
            for (int d = 0; d < 8; ++d) acc[i][d] *= corr;

            #pragma unroll
            for (int j = 0; j < 8; ++j)
                Ps[(ty + 16 * i) * PADW + tx + 16 * j] = sreg[i][j];
        }
        __syncthreads();

        // ---- GEMM2: O[4][8] += P(rows ty+16i) . V (d-cols tx+16d) ----
        #pragma unroll 2
        for (int n = 0; n < BN; n += 4) {
            float p4[4][4];
            #pragma unroll
            for (int i = 0; i < 4; ++i)
                *(float4*)p4[i] = *(const float4*)&Ps[(ty + 16 * i) * PADW + n];
            #pragma unroll
            for (int e = 0; e < 4; ++e) {
                float vv[8];
                #pragma unroll
                for (int d = 0; d < 8; ++d)
                    vv[d] = Vs[(n + e) * PADW + tx + 16 * d];
                #pragma unroll
                for (int i = 0; i < 4; ++i) {
                    const float p = p4[i][e];
                    #pragma unroll
                    for (int d = 0; d < 8; ++d)
                        acc[i][d] = fmaf(p, vv[d], acc[i][d]);
                }
            }
        }
        __syncthreads();
    }

    // ---- epilogue: normalize and store o[t][h*128 + d] ----
    #pragma unroll
    for (int i = 0; i < 4; ++i) {
        const int t = b * SEQ + qt * BM + ty + 16 * i;
        const float inv = 1.0f / li[i];
        float* dst = o + (size_t)t * (NHEADS * HDIM) + (size_t)h * HDIM;
        #pragma unroll
        for (int d = 0; d < 8; ++d)
            dst[tx + 16 * d] = acc[i][d] * inv;
    }
}

// ---------------------------------------------------------------------------
// Copy input caches into the output buffer (output is poisoned by harness).
// ---------------------------------------------------------------------------
__global__ void copy_caches_kernel(const float4* __restrict__ kc,
                                   const float4* __restrict__ vc,
                                   float4* __restrict__ okc,
                                   float4* __restrict__ ovc,
                                   int n4)
{
    const int i = blockIdx.x * blockDim.x + threadIdx.x;
    if (i < n4) {
        okc[i] = kc[i];
        ovc[i] = vc[i];
    }
}

// ---------------------------------------------------------------------------
// Scatter new K/V into the paged caches per slot_mapping (after copy).
// One block per token; 256 threads x float4 = 1024 floats = NKV*HDIM.
// ---------------------------------------------------------------------------
__global__ void scatter_kv_kernel(const float* __restrict__ k,
                                  const float* __restrict__ v,
                                  const int* __restrict__ slot_mapping,
                                  float* __restrict__ okc,
                                  float* __restrict__ ovc)
{
    const int t = blockIdx.x;
    const int s = slot_mapping[t];
    if (s < 0) return;
    if ((s >> 8) >= NBLOCKS) return;   // block index out of range -> drop

    const int tid = threadIdx.x;
    const float4* ks = (const float4*)(k + (size_t)t * NKV * HDIM);
    const float4* vs = (const float4*)(v + (size_t)t * NKV * HDIM);
    float4* kd = (float4*)(okc + (size_t)s * NKV * HDIM);
    float4* vd = (float4*)(ovc + (size_t)s * NKV * HDIM);
    kd[tid] = ks[tid];
    vd[tid] = vs[tid];
}

// ---------------------------------------------------------------------------
// kernel_launch: inputs in metadata order
//   0 q [4096,32,128] f32, 1 k [4096,8,128] f32, 2 v [4096,8,128] f32,
//   3 k_cache [32,256,8,128] f32, 4 v_cache, 5 slot_mapping [4096] i32,
//   6 cu_seqlens_q [5] i32 (unused, uniform), 7 cu_seqlens_k (unused)
// output: concat(o [4096,4096], k_cache, v_cache) f32
// ---------------------------------------------------------------------------
extern "C" void kernel_launch(void* const* d_in, const int* in_sizes, int n_in,
                              void* d_out, int out_size)
{
    const float* q    = (const float*)d_in[0];
    const float* k    = (const float*)d_in[1];
    const float* v    = (const float*)d_in[2];
    const float* kc   = (const float*)d_in[3];
    const float* vc   = (const float*)d_in[4];
    const int*   slot = (const int*)d_in[5];

    float* out = (float*)d_out;
    float* o   = out;
    float* okc = out + O_ELEMS;
    float* ovc = okc + CACHE_ELEMS;

    cudaFuncSetAttribute(flash_attn_kernel,
                         cudaFuncAttributeMaxDynamicSharedMemorySize, SMEM_BYTES);

    dim3 grid(SEQ / BM, NHEADS, BATCH);
    flash_attn_kernel<<<grid, NTHREADS, SMEM_BYTES>>>(q, k, v, o);

    const int n4 = (int)(CACHE_ELEMS / 4);
    copy_caches_kernel<<<(n4 + 255) / 256, 256>>>(
        (const float4*)kc, (const float4*)vc, (float4*)okc, (float4*)ovc, n4);

    scatter_kv_kernel<<<NTOK, 256>>>(k, v, slot, okc, ovc);
}

// round 5
// speedup vs baseline: 1.3169x; 1.3169x over previous
#include <cuda_runtime.h>
#include <cstdint>
#include <cstddef>

// Problem constants (fixed shapes)
#define BATCH   4
#define SEQ     1024
#define NHEADS  32
#define NKV     8
#define HDIM    128
#define NTOK    (BATCH * SEQ)
#define NBLOCKS 32
#define BLOCKSZ 256

#define BM 128         // q rows per CTA (8 warps x 16 rows)
#define BN 64          // keys per iteration
#define NTHREADS 256

// scale = float(bfloat16(1/sqrt(128))) = 0x3DB50000
#define ATTN_SCALE 0.08837890625f

#define O_ELEMS     ((size_t)NTOK * NHEADS * HDIM)           // 16,777,216
#define CACHE_ELEMS ((size_t)NBLOCKS * BLOCKSZ * NKV * HDIM) // 8,388,608

// Shared-memory fragment stores (all tf32 bit patterns, stored as u32):
//  Qf: per (warp, kc=0..15, lane, reg=0..3)   -> A frags of Q, LDS.128 per (warp,kc)
//  Kf: per (kc=0..15, r=0..1, nt=0..7, lane)  -> B frags of K, LDS.32  per (kc,r,nt)
//  Vf: per (kc2=0..7, nt2=0..15, lane, r)     -> B frags of V, LDS.64  per (kc2,nt2)
#define QF_U32 (BM * HDIM)        // 16384
#define KF_U32 (16 * 2 * 8 * 32)  // 8192
#define VF_U32 (8 * 16 * 32 * 2)  // 8192
#define SMEM_BYTES ((QF_U32 + KF_U32 + VF_U32) * 4)  // 131072

__device__ __forceinline__ uint32_t f2tf32(float f) {
    uint32_t u;
    asm("cvt.rna.tf32.f32 %0, %1;" : "=r"(u) : "f"(f));
    return u;
}

__device__ __forceinline__ void mma_tf32(float c[4],
                                         uint32_t a0, uint32_t a1, uint32_t a2, uint32_t a3,
                                         uint32_t b0, uint32_t b1) {
    asm volatile(
        "mma.sync.aligned.m16n8k8.row.col.f32.tf32.tf32.f32 "
        "{%0,%1,%2,%3}, {%4,%5,%6,%7}, {%8,%9}, {%0,%1,%2,%3};"
        : "+f"(c[0]), "+f"(c[1]), "+f"(c[2]), "+f"(c[3])
        : "r"(a0), "r"(a1), "r"(a2), "r"(a3), "r"(b0), "r"(b1));
}

// ---------------------------------------------------------------------------
// Flash attention (causal, GQA 4:1), TF32 tensor cores, fp32 softmax.
// grid = (SEQ/BM, NHEADS, BATCH), block = 256 (8 warps, 16 q-rows each).
// ---------------------------------------------------------------------------
__global__ __launch_bounds__(NTHREADS, 1)
void flash_attn_tc(const float* __restrict__ q,
                   const float* __restrict__ k,
                   const float* __restrict__ v,
                   float* __restrict__ o)
{
    extern __shared__ float smem[];
    uint32_t* Qf = (uint32_t*)smem;
    uint32_t* Kf = Qf + QF_U32;
    uint32_t* Vf = Kf + KF_U32;

    const int qt  = gridDim.x - 1 - blockIdx.x;   // heavy CTAs launch first
    const int h   = blockIdx.y;
    const int b   = blockIdx.z;
    const int kvh = h >> 2;                       // GQA: 4 q-heads per kv-head

    const int tid  = threadIdx.x;
    const int warp = tid >> 5;
    const int lane = tid & 31;
    const int g    = lane >> 2;   // groupID
    const int tg   = lane & 3;    // threadID in group

    // ---- stage Q once: A-fragment layout, tf32 ----
    // A frag (m16n8k8, row-major 16x8): a0=(g, tg) a1=(g+8, tg) a2=(g, tg+4) a3=(g+8, tg+4)
    {
        const float* qbase = q + ((size_t)(b * SEQ + qt * BM) * NHEADS + h) * HDIM;
        #pragma unroll 4
        for (int it = 0; it < QF_U32 / NTHREADS; ++it) {
            const int idx = tid + it * NTHREADS;
            const int reg = idx & 3;
            const int ln  = (idx >> 2) & 31;
            const int kc  = (idx >> 7) & 15;
            const int w   = idx >> 11;
            const int R = w * 16 + (ln >> 2) + 8 * (reg & 1);
            const int C = kc * 8 + (ln & 3) + 4 * (reg >> 1);
            Qf[idx] = f2tf32(qbase[(size_t)R * NHEADS * HDIM + C]);
        }
    }

    float oacc[16][4];   // O[16 rows x 128 d] per warp: 16 n-tiles of m16n8 C frags
    #pragma unroll
    for (int t = 0; t < 16; ++t) {
        oacc[t][0] = 0.f; oacc[t][1] = 0.f; oacc[t][2] = 0.f; oacc[t][3] = 0.f;
    }
    float mi0 = -1e30f, mi1 = -1e30f, li0 = 0.f, li1 = 0.f;

    const int nkt  = 2 * (qt + 1);
    const int row0 = qt * BM + warp * 16 + g;   // global q row of C-frag row g
    const int row1 = row0 + 8;

    for (int kt = 0; kt < nkt; ++kt) {
        const int n0 = kt * BN;
        __syncthreads();

        // ---- stage K tile: B frags (kc, r, nt, lane): K[8nt + (lane>>2)][8kc + (lane&3) + 4r]
        {
            const float* kbase = k + ((size_t)(b * SEQ + n0) * NKV + kvh) * HDIM;
            #pragma unroll 4
            for (int it = 0; it < KF_U32 / NTHREADS; ++it) {
                const int idx = tid + it * NTHREADS;
                const int ln = idx & 31;
                const int nt = (idx >> 5) & 7;
                const int r  = (idx >> 8) & 1;
                const int kc = idx >> 9;
                const int key = nt * 8 + (ln >> 2);
                const int d   = kc * 8 + (ln & 3) + 4 * r;
                Kf[idx] = f2tf32(kbase[(size_t)key * NKV * HDIM + d]);
            }
            // ---- stage V tile: B frags (kc2, nt2, lane, r): V[8kc2 + (lane&3) + 4r][8nt2 + (lane>>2)]
            const float* vbase = v + ((size_t)(b * SEQ + n0) * NKV + kvh) * HDIM;
            #pragma unroll 4
            for (int it = 0; it < VF_U32 / NTHREADS; ++it) {
                const int idx = tid + it * NTHREADS;
                const int r   = idx & 1;
                const int ln  = (idx >> 1) & 31;
                const int nt2 = (idx >> 6) & 15;
                const int kc2 = idx >> 10;
                const int key = kc2 * 8 + (ln & 3) + 4 * r;
                const int d   = nt2 * 8 + (ln >> 2);
                Vf[idx] = f2tf32(vbase[(size_t)key * NKV * HDIM + d]);
            }
        }
        __syncthreads();

        // ---- GEMM1: S[16 x 64] = Q . K^T (tf32 MMA) ----
        float s[8][4];
        #pragma unroll
        for (int nt = 0; nt < 8; ++nt) {
            s[nt][0] = 0.f; s[nt][1] = 0.f; s[nt][2] = 0.f; s[nt][3] = 0.f;
        }
        #pragma unroll
        for (int kc = 0; kc < 16; ++kc) {
            uint32_t a[4];
            *(uint4*)a = *(const uint4*)&Qf[(((warp * 16 + kc) * 32) + lane) * 4];
            #pragma unroll
            for (int nt = 0; nt < 8; ++nt) {
                const uint32_t b0 = Kf[((kc * 2 + 0) * 8 + nt) * 32 + lane];
                const uint32_t b1 = Kf[((kc * 2 + 1) * 8 + nt) * 32 + lane];
                mma_tf32(s[nt], a[0], a[1], a[2], a[3], b0, b1);
            }
        }

        // ---- scale + causal mask + online softmax (fp32) ----
        // C frag rows: reg{0,1}->row0, reg{2,3}->row1; cols: 8nt + 2tg (+1)
        const bool need_mask = (kt >= 2 * qt);
        float rmax0 = -1e30f, rmax1 = -1e30f;
        #pragma unroll
        for (int nt = 0; nt < 8; ++nt) {
            const int c0 = n0 + nt * 8 + 2 * tg;
            #pragma unroll
            for (int e = 0; e < 4; ++e) {
                float sv = s[nt][e] * ATTN_SCALE;
                if (need_mask) {
                    const int cc = c0 + (e & 1);
                    const int rr = (e < 2) ? row0 : row1;
                    if (cc > rr) sv = -1e30f;
                }
                s[nt][e] = sv;
            }
            rmax0 = fmaxf(rmax0, fmaxf(s[nt][0], s[nt][1]));
            rmax1 = fmaxf(rmax1, fmaxf(s[nt][2], s[nt][3]));
        }
        rmax0 = fmaxf(rmax0, __shfl_xor_sync(0xffffffffu, rmax0, 1));
        rmax0 = fmaxf(rmax0, __shfl_xor_sync(0xffffffffu, rmax0, 2));
        rmax1 = fmaxf(rmax1, __shfl_xor_sync(0xffffffffu, rmax1, 1));
        rmax1 = fmaxf(rmax1, __shfl_xor_sync(0xffffffffu, rmax1, 2));

        const float mn0 = fmaxf(mi0, rmax0);
        const float mn1 = fmaxf(mi1, rmax1);
        const float corr0 = __expf(mi0 - mn0);
        const float corr1 = __expf(mi1 - mn1);
        mi0 = mn0; mi1 = mn1;

        uint32_t ps[8][4];   // P in tf32 bits, same C-frag layout as s
        float rs0 = 0.f, rs1 = 0.f;
        #pragma unroll
        for (int nt = 0; nt < 8; ++nt) {
            const float p0 = __expf(s[nt][0] - mn0);
            const float p1 = __expf(s[nt][1] - mn0);
            const float p2 = __expf(s[nt][2] - mn1);
            const float p3 = __expf(s[nt][3] - mn1);
            rs0 += p0 + p1; rs1 += p2 + p3;
            ps[nt][0] = f2tf32(p0); ps[nt][1] = f2tf32(p1);
            ps[nt][2] = f2tf32(p2); ps[nt][3] = f2tf32(p3);
        }
        rs0 += __shfl_xor_sync(0xffffffffu, rs0, 1);
        rs0 += __shfl_xor_sync(0xffffffffu, rs0, 2);
        rs1 += __shfl_xor_sync(0xffffffffu, rs1, 1);
        rs1 += __shfl_xor_sync(0xffffffffu, rs1, 2);
        li0 = li0 * corr0 + rs0;
        li1 = li1 * corr1 + rs1;
        #pragma unroll
        for (int t = 0; t < 16; ++t) {
            oacc[t][0] *= corr0; oacc[t][1] *= corr0;
            oacc[t][2] *= corr1; oacc[t][3] *= corr1;
        }

        // ---- GEMM2: O[16 x 128] += P . V ----
        // C-frag(P) -> A-frag relayout via intra-warp shuffles (P is warp-private).
        // A col j owner in C layout: src tg' = j>>1, reg parity j&1.
        const int src0 = (lane & ~3) | (tg >> 1);   // for A cols tg   (j = tg)
        const int src1 = src0 + 2;                  // for A cols tg+4 (j = tg+4)
        #pragma unroll
        for (int kc2 = 0; kc2 < 8; ++kc2) {
            const uint32_t t00 = __shfl_sync(0xffffffffu, ps[kc2][0], src0);
            const uint32_t t01 = __shfl_sync(0xffffffffu, ps[kc2][1], src0);
            const uint32_t t10 = __shfl_sync(0xffffffffu, ps[kc2][2], src0);
            const uint32_t t11 = __shfl_sync(0xffffffffu, ps[kc2][3], src0);
            const uint32_t u00 = __shfl_sync(0xffffffffu, ps[kc2][0], src1);
            const uint32_t u01 = __shfl_sync(0xffffffffu, ps[kc2][1], src1);
            const uint32_t u10 = __shfl_sync(0xffffffffu, ps[kc2][2], src1);
            const uint32_t u11 = __shfl_sync(0xffffffffu, ps[kc2][3], src1);
            const uint32_t a0 = (tg & 1) ? t01 : t00;   // row g,   col tg
            const uint32_t a1 = (tg & 1) ? t11 : t10;   // row g+8, col tg
            const uint32_t a2 = (tg & 1) ? u01 : u00;   // row g,   col tg+4
            const uint32_t a3 = (tg & 1) ? u11 : u10;   // row g+8, col tg+4
            #pragma unroll
            for (int nt2 = 0; nt2 < 16; ++nt2) {
                uint32_t bb[2];
                *(uint2*)bb = *(const uint2*)&Vf[((kc2 * 16 + nt2) * 32 + lane) * 2];
                mma_tf32(oacc[nt2], a0, a1, a2, a3, bb[0], bb[1]);
            }
        }
    }

    // ---- epilogue: normalize, store ----
    const float inv0 = 1.0f / li0;
    const float inv1 = 1.0f / li1;
    float* ob = o + ((size_t)(b * SEQ + row0) * NHEADS + h) * HDIM;
    #pragma unroll
    for (int nt2 = 0; nt2 < 16; ++nt2) {
        const int d = nt2 * 8 + 2 * tg;
        float2 v0; v0.x = oacc[nt2][0] * inv0; v0.y = oacc[nt2][1] * inv0;
        float2 v1; v1.x = oacc[nt2][2] * inv1; v1.y = oacc[nt2][3] * inv1;
        *(float2*)&ob[d] = v0;
        *(float2*)&ob[(size_t)8 * NHEADS * HDIM + d] = v1;
    }
}

// ---------------------------------------------------------------------------
// Copy input caches into the output buffer (output is poisoned by harness).
// ---------------------------------------------------------------------------
__global__ void copy_caches_kernel(const float4* __restrict__ kc,
                                   const float4* __restrict__ vc,
                                   float4* __restrict__ okc,
                                   float4* __restrict__ ovc,
                                   int n4)
{
    const int i = blockIdx.x * blockDim.x + threadIdx.x;
    if (i < n4) {
        okc[i] = kc[i];
        ovc[i] = vc[i];
    }
}

// ---------------------------------------------------------------------------
// Scatter new K/V into the paged caches per slot_mapping (after copy).
// ---------------------------------------------------------------------------
__global__ void scatter_kv_kernel(const float* __restrict__ k,
                                  const float* __restrict__ v,
                                  const int* __restrict__ slot_mapping,
                                  float* __restrict__ okc,
                                  float* __restrict__ ovc)
{
    const int t = blockIdx.x;
    const int s = slot_mapping[t];
    if (s < 0) return;
    if ((s >> 8) >= NBLOCKS) return;   // block index out of range -> drop

    const int tid = threadIdx.x;
    const float4* ks = (const float4*)(k + (size_t)t * NKV * HDIM);
    const float4* vs = (const float4*)(v + (size_t)t * NKV * HDIM);
    float4* kd = (float4*)(okc + (size_t)s * NKV * HDIM);
    float4* vd = (float4*)(ovc + (size_t)s * NKV * HDIM);
    kd[tid] = ks[tid];
    vd[tid] = vs[tid];
}

// ---------------------------------------------------------------------------
// kernel_launch: inputs in metadata order
//   0 q, 1 k, 2 v, 3 k_cache, 4 v_cache, 5 slot_mapping, 6/7 cu_seqlens (unused)
// output: concat(o [4096,4096], k_cache, v_cache) f32
// ---------------------------------------------------------------------------
extern "C" void kernel_launch(void* const* d_in, const int* in_sizes, int n_in,
                              void* d_out, int out_size)
{
    const float* q    = (const float*)d_in[0];
    const float* k    = (const float*)d_in[1];
    const float* v    = (const float*)d_in[2];
    const float* kc   = (const float*)d_in[3];
    const float* vc   = (const float*)d_in[4];
    const int*   slot = (const int*)d_in[5];

    float* out = (float*)d_out;
    float* o   = out;
    float* okc = out + O_ELEMS;
    float* ovc = okc + CACHE_ELEMS;

    cudaFuncSetAttribute(flash_attn_tc,
                         cudaFuncAttributeMaxDynamicSharedMemorySize, SMEM_BYTES);

    dim3 grid(SEQ / BM, NHEADS, BATCH);
    flash_attn_tc<<<grid, NTHREADS, SMEM_BYTES>>>(q, k, v, o);

    const int n4 = (int)(CACHE_ELEMS / 4);
    copy_caches_kernel<<<(n4 + 255) / 256, 256>>>(
        (const float4*)kc, (const float4*)vc, (float4*)okc, (float4*)ovc, n4);

    scatter_kv_kernel<<<NTOK, 256>>>(k, v, slot, okc, ovc);
}

// round 6
// speedup vs baseline: 2.6241x; 1.9926x over previous
#include <cuda_runtime.h>
#include <cstdint>
#include <cstddef>

// Problem constants (fixed shapes)
#define BATCH   4
#define SEQ     1024
#define NHEADS  32
#define NKV     8
#define HDIM    128
#define NTOK    (BATCH * SEQ)
#define NBLOCKS 32
#define BLOCKSZ 256

#define BM 128         // q rows per CTA (8 warps x 16 rows)
#define BN 64          // keys per iteration
#define NTHREADS 256
#define PADW 136       // padded row stride (floats); 136 mod 32 = 8 -> conflict-free frag LDS

// scale = float(bfloat16(1/sqrt(128))) = 0.08837890625; folded with log2(e)
#define SCALE_LOG2E 0.1274994096f

#define O_ELEMS     ((size_t)NTOK * NHEADS * HDIM)           // 16,777,216
#define CACHE_ELEMS ((size_t)NBLOCKS * BLOCKSZ * NKV * HDIM) // 8,388,608

// smem: KS[2][BN][PADW] + VS[2][BN][PADW] raw fp32, double-buffered
#define TILE_F   (BN * PADW)                 // 8704 floats
#define SMEM_F   (4 * TILE_F)                // 34816 floats
#define SMEM_BYTES (SMEM_F * 4)              // 139,264 B

__device__ __forceinline__ uint32_t f2tf32(float f) {
    uint32_t u;
    asm("cvt.rna.tf32.f32 %0, %1;" : "=r"(u) : "f"(f));
    return u;
}

__device__ __forceinline__ float fexp2(float x) {
    float y;
    asm("ex2.approx.f32 %0, %1;" : "=f"(y) : "f"(x));
    return y;
}

__device__ __forceinline__ void mma_tf32(float c[4],
                                         uint32_t a0, uint32_t a1, uint32_t a2, uint32_t a3,
                                         uint32_t b0, uint32_t b1) {
    asm volatile(
        "mma.sync.aligned.m16n8k8.row.col.f32.tf32.tf32.f32 "
        "{%0,%1,%2,%3}, {%4,%5,%6,%7}, {%8,%9}, {%0,%1,%2,%3};"
        : "+f"(c[0]), "+f"(c[1]), "+f"(c[2]), "+f"(c[3])
        : "r"(a0), "r"(a1), "r"(a2), "r"(a3), "r"(b0), "r"(b1));
}

__device__ __forceinline__ void cp16(uint32_t dst, const float* src) {
    asm volatile("cp.async.cg.shared.global [%0], [%1], 16;" :: "r"(dst), "l"(src));
}

// ---------------------------------------------------------------------------
// Flash attention (causal, GQA 4:1), TF32 tensor cores, fp32 softmax,
// cp.async double-buffered K/V, Q fragments in registers.
// grid = (SEQ/BM, NHEADS, BATCH), block = 256 (8 warps, 16 q-rows each).
// ---------------------------------------------------------------------------
__global__ __launch_bounds__(NTHREADS, 1)
void flash_attn_tc(const float* __restrict__ q,
                   const float* __restrict__ k,
                   const float* __restrict__ v,
                   float* __restrict__ o)
{
    extern __shared__ float smem[];
    float* KS = smem;                 // [2][BN][PADW]
    float* VS = smem + 2 * TILE_F;    // [2][BN][PADW]
    const uint32_t ks_base = (uint32_t)__cvta_generic_to_shared(KS);
    const uint32_t vs_base = (uint32_t)__cvta_generic_to_shared(VS);

    const int qt  = (int)gridDim.x - 1 - (int)blockIdx.x;  // heavy CTAs first
    const int h   = blockIdx.y;
    const int b   = blockIdx.z;
    const int kvh = h >> 2;                                 // GQA: N_REP=4

    const int tid  = threadIdx.x;
    const int warp = tid >> 5;
    const int lane = tid & 31;
    const int g    = lane >> 2;   // groupID (C/A frag row within 8)
    const int tg   = lane & 3;    // thread-in-group

    const float* kbatch = k + ((size_t)(b * SEQ) * NKV + kvh) * HDIM;
    const float* vbatch = v + ((size_t)(b * SEQ) * NKV + kvh) * HDIM;

    // ---- Q fragments into registers (A frags m16n8k8, tf32), loaded once ----
    // a_e = Q[warp*16 + g + 8*(e&1)][kc*8 + tg + 4*(e>>1)]
    uint32_t qa[16][4];
    {
        const float* qbase = q + ((size_t)(b * SEQ + qt * BM + warp * 16) * NHEADS + h) * HDIM;
        #pragma unroll
        for (int kc = 0; kc < 16; ++kc) {
            #pragma unroll
            for (int e = 0; e < 4; ++e) {
                const int R = g + 8 * (e & 1);
                const int C = kc * 8 + tg + 4 * (e >> 1);
                qa[kc][e] = f2tf32(qbase[(size_t)R * NHEADS * HDIM + C]);
            }
        }
    }

    float oacc[16][4];   // O[16 rows x 128 d]: 16 n-tiles of m16n8 C frags
    #pragma unroll
    for (int t = 0; t < 16; ++t) {
        oacc[t][0] = 0.f; oacc[t][1] = 0.f; oacc[t][2] = 0.f; oacc[t][3] = 0.f;
    }
    float mi0 = -1e30f, mi1 = -1e30f, li0 = 0.f, li1 = 0.f;

    const int nkt   = 2 * (qt + 1);
    const int wbase = qt * BM + warp * 16;    // first global q row of this warp
    const int row0  = wbase + g;
    const int row1  = row0 + 8;

    // chunk mapping for cp.async staging: 8 x 16B per thread per tensor
    const int st_r = tid >> 5;          // rows tid/32 + 8*it  (8 rows per pass of 256 thr? no:)
    // actually: idx = tid + it*256 -> r = idx>>5 (0..63), c = (idx&31)*4
    // (computed inline below)

    // ---- prologue: stage tile 0 into buffer 0 ----
    {
        const float* kb = kbatch;
        const float* vb = vbatch;
        #pragma unroll
        for (int it = 0; it < 8; ++it) {
            const int idx = tid + it * NTHREADS;
            const int r = idx >> 5;
            const int c = (idx & 31) * 4;
            cp16(ks_base + (uint32_t)(r * PADW + c) * 4, kb + (size_t)r * NKV * HDIM + c);
            cp16(vs_base + (uint32_t)(r * PADW + c) * 4, vb + (size_t)r * NKV * HDIM + c);
        }
        asm volatile("cp.async.commit_group;");
    }

    for (int kt = 0; kt < nkt; ++kt) {
        const int n0 = kt * BN;

        // ---- prefetch next tile into the other buffer ----
        if (kt + 1 < nkt) {
            const int nbuf = (kt + 1) & 1;
            const float* kb = kbatch + (size_t)(n0 + BN) * NKV * HDIM;
            const float* vb = vbatch + (size_t)(n0 + BN) * NKV * HDIM;
            const uint32_t kd = ks_base + (uint32_t)(nbuf * TILE_F) * 4;
            const uint32_t vd = vs_base + (uint32_t)(nbuf * TILE_F) * 4;
            #pragma unroll
            for (int it = 0; it < 8; ++it) {
                const int idx = tid + it * NTHREADS;
                const int r = idx >> 5;
                const int c = (idx & 31) * 4;
                cp16(kd + (uint32_t)(r * PADW + c) * 4, kb + (size_t)r * NKV * HDIM + c);
                cp16(vd + (uint32_t)(r * PADW + c) * 4, vb + (size_t)r * NKV * HDIM + c);
            }
        }
        asm volatile("cp.async.commit_group;");
        asm volatile("cp.async.wait_group 1;");
        __syncthreads();

        // warps whose rows are all < n0 have a fully-masked tile: skip compute
        if (n0 <= wbase + 15) {
            const float* Kt = KS + (kt & 1) * TILE_F;
            const float* Vt = VS + (kt & 1) * TILE_F;

            // ---- GEMM1: S[16 x 64] = Q . K^T ----
            float s[8][4];
            #pragma unroll
            for (int nt = 0; nt < 8; ++nt) {
                s[nt][0] = 0.f; s[nt][1] = 0.f; s[nt][2] = 0.f; s[nt][3] = 0.f;
            }
            #pragma unroll
            for (int kc = 0; kc < 16; ++kc) {
                #pragma unroll
                for (int nt = 0; nt < 8; ++nt) {
                    const float* kp = &Kt[(nt * 8 + g) * PADW + kc * 8 + tg];
                    const uint32_t b0 = f2tf32(kp[0]);
                    const uint32_t b1 = f2tf32(kp[4]);
                    mma_tf32(s[nt], qa[kc][0], qa[kc][1], qa[kc][2], qa[kc][3], b0, b1);
                }
            }

            // ---- scale(+log2e) + causal mask + online softmax (base-2) ----
            const bool need_mask = (n0 + BN - 1 > wbase);
            float rmax0 = -1e30f, rmax1 = -1e30f;
            #pragma unroll
            for (int nt = 0; nt < 8; ++nt) {
                const int c0 = n0 + nt * 8 + 2 * tg;
                #pragma unroll
                for (int e = 0; e < 4; ++e) {
                    float sv = s[nt][e] * SCALE_LOG2E;
                    if (need_mask) {
                        const int cc = c0 + (e & 1);
                        const int rr = (e < 2) ? row0 : row1;
                        if (cc > rr) sv = -1e30f;
                    }
                    s[nt][e] = sv;
                }
                rmax0 = fmaxf(rmax0, fmaxf(s[nt][0], s[nt][1]));
                rmax1 = fmaxf(rmax1, fmaxf(s[nt][2], s[nt][3]));
            }
            rmax0 = fmaxf(rmax0, __shfl_xor_sync(0xffffffffu, rmax0, 1));
            rmax0 = fmaxf(rmax0, __shfl_xor_sync(0xffffffffu, rmax0, 2));
            rmax1 = fmaxf(rmax1, __shfl_xor_sync(0xffffffffu, rmax1, 1));
            rmax1 = fmaxf(rmax1, __shfl_xor_sync(0xffffffffu, rmax1, 2));

            const float mn0 = fmaxf(mi0, rmax0);
            const float mn1 = fmaxf(mi1, rmax1);
            const float corr0 = fexp2(mi0 - mn0);
            const float corr1 = fexp2(mi1 - mn1);
            mi0 = mn0; mi1 = mn1;

            uint32_t ps[8][4];   // P in tf32 bits, C-frag layout
            float rs0 = 0.f, rs1 = 0.f;
            #pragma unroll
            for (int nt = 0; nt < 8; ++nt) {
                const float p0 = fexp2(s[nt][0] - mn0);
                const float p1 = fexp2(s[nt][1] - mn0);
                const float p2 = fexp2(s[nt][2] - mn1);
                const float p3 = fexp2(s[nt][3] - mn1);
                rs0 += p0 + p1; rs1 += p2 + p3;
                ps[nt][0] = f2tf32(p0); ps[nt][1] = f2tf32(p1);
                ps[nt][2] = f2tf32(p2); ps[nt][3] = f2tf32(p3);
            }
            rs0 += __shfl_xor_sync(0xffffffffu, rs0, 1);
            rs0 += __shfl_xor_sync(0xffffffffu, rs0, 2);
            rs1 += __shfl_xor_sync(0xffffffffu, rs1, 1);
            rs1 += __shfl_xor_sync(0xffffffffu, rs1, 2);
            li0 = li0 * corr0 + rs0;
            li1 = li1 * corr1 + rs1;
            #pragma unroll
            for (int t = 0; t < 16; ++t) {
                oacc[t][0] *= corr0; oacc[t][1] *= corr0;
                oacc[t][2] *= corr1; oacc[t][3] *= corr1;
            }

            // ---- GEMM2: O[16 x 128] += P . V ----
            // C-frag(P) -> A-frag relayout via intra-warp shuffles.
            const int src0 = (lane & ~3) | (tg >> 1);
            const int src1 = src0 + 2;
            #pragma unroll
            for (int kc2 = 0; kc2 < 8; ++kc2) {
                const uint32_t t00 = __shfl_sync(0xffffffffu, ps[kc2][0], src0);
                const uint32_t t01 = __shfl_sync(0xffffffffu, ps[kc2][1], src0);
                const uint32_t t10 = __shfl_sync(0xffffffffu, ps[kc2][2], src0);
                const uint32_t t11 = __shfl_sync(0xffffffffu, ps[kc2][3], src0);
                const uint32_t u00 = __shfl_sync(0xffffffffu, ps[kc2][0], src1);
                const uint32_t u01 = __shfl_sync(0xffffffffu, ps[kc2][1], src1);
                const uint32_t u10 = __shfl_sync(0xffffffffu, ps[kc2][2], src1);
                const uint32_t u11 = __shfl_sync(0xffffffffu, ps[kc2][3], src1);
                const uint32_t a0 = (tg & 1) ? t01 : t00;
                const uint32_t a1 = (tg & 1) ? t11 : t10;
                const uint32_t a2 = (tg & 1) ? u01 : u00;
                const uint32_t a3 = (tg & 1) ? u11 : u10;
                #pragma unroll
                for (int nt2 = 0; nt2 < 16; ++nt2) {
                    const float* vp = &Vt[(kc2 * 8 + tg) * PADW + nt2 * 8 + g];
                    const uint32_t b0 = f2tf32(vp[0]);
                    const uint32_t b1 = f2tf32(vp[4 * PADW]);
                    mma_tf32(oacc[nt2], a0, a1, a2, a3, b0, b1);
                }
            }
        }
        __syncthreads();   // all warps done reading this buffer before reuse
    }

    // ---- epilogue: normalize, store ----
    const float inv0 = 1.0f / li0;
    const float inv1 = 1.0f / li1;
    float* ob = o + ((size_t)(b * SEQ + row0) * NHEADS + h) * HDIM;
    #pragma unroll
    for (int nt2 = 0; nt2 < 16; ++nt2) {
        const int d = nt2 * 8 + 2 * tg;
        float2 v0; v0.x = oacc[nt2][0] * inv0; v0.y = oacc[nt2][1] * inv0;
        float2 v1; v1.x = oacc[nt2][2] * inv1; v1.y = oacc[nt2][3] * inv1;
        *(float2*)&ob[d] = v0;
        *(float2*)&ob[(size_t)8 * NHEADS * HDIM + d] = v1;
    }
}

// ---------------------------------------------------------------------------
// Copy input caches into the output buffer (output is poisoned by harness).
// ---------------------------------------------------------------------------
__global__ void copy_caches_kernel(const float4* __restrict__ kc,
                                   const float4* __restrict__ vc,
                                   float4* __restrict__ okc,
                                   float4* __restrict__ ovc,
                                   int n4)
{
    const int i = blockIdx.x * blockDim.x + threadIdx.x;
    if (i < n4) {
        okc[i] = kc[i];
        ovc[i] = vc[i];
    }
}

// ---------------------------------------------------------------------------
// Scatter new K/V into the paged caches per slot_mapping (after copy).
// ---------------------------------------------------------------------------
__global__ void scatter_kv_kernel(const float* __restrict__ k,
                                  const float* __restrict__ v,
                                  const int* __restrict__ slot_mapping,
                                  float* __restrict__ okc,
                                  float* __restrict__ ovc)
{
    const int t = blockIdx.x;
    const int s = slot_mapping[t];
    if (s < 0) return;
    if ((s >> 8) >= NBLOCKS) return;   // block index out of range -> drop

    const int tid = threadIdx.x;
    const float4* ks = (const float4*)(k + (size_t)t * NKV * HDIM);
    const float4* vs = (const float4*)(v + (size_t)t * NKV * HDIM);
    float4* kd = (float4*)(okc + (size_t)s * NKV * HDIM);
    float4* vd = (float4*)(ovc + (size_t)s * NKV * HDIM);
    kd[tid] = ks[tid];
    vd[tid] = vs[tid];
}

// ---------------------------------------------------------------------------
// kernel_launch: inputs in metadata order
//   0 q, 1 k, 2 v, 3 k_cache, 4 v_cache, 5 slot_mapping, 6/7 cu_seqlens (unused)
// output: concat(o [4096,4096], k_cache, v_cache) f32
// ---------------------------------------------------------------------------
extern "C" void kernel_launch(void* const* d_in, const int* in_sizes, int n_in,
                              void* d_out, int out_size)
{
    const float* q    = (const float*)d_in[0];
    const float* k    = (const float*)d_in[1];
    const float* v    = (const float*)d_in[2];
    const float* kc   = (const float*)d_in[3];
    const float* vc   = (const float*)d_in[4];
    const int*   slot = (const int*)d_in[5];

    float* out = (float*)d_out;
    float* o   = out;
    float* okc = out + O_ELEMS;
    float* ovc = okc + CACHE_ELEMS;

    cudaFuncSetAttribute(flash_attn_tc,
                         cudaFuncAttributeMaxDynamicSharedMemorySize, SMEM_BYTES);

    dim3 grid(SEQ / BM, NHEADS, BATCH);
    flash_attn_tc<<<grid, NTHREADS, SMEM_BYTES>>>(q, k, v, o);

    const int n4 = (int)(CACHE_ELEMS / 4);
    copy_caches_kernel<<<(n4 + 255) / 256, 256>>>(
        (const float4*)kc, (const float4*)vc, (float4*)okc, (float4*)ovc, n4);

    scatter_kv_kernel<<<NTOK, 256>>>(k, v, slot, okc, ovc);
}